// round 2
// baseline (speedup 1.0000x reference)
#include <cuda_runtime.h>

// Problem dims
#define NB  16
#define CCH 256
#define TT  256
#define VV  25
#define VPN 20
#define SS  3
#define ICN 64
#define CT   (CCH*TT)      // 65536
#define NCOL (TT*VPN)      // 5120
#define M1 384             // fa|fb stacked rows
#define KK1 256
#define M2 256
#define KK2 768

// ---------------- scratch (device globals; no runtime allocation) -------------
__device__ float g_xp[(size_t)NB*CT*VPN];        // (N, C*T, VP)   84MB
__device__ float g_fab[(size_t)NB*M1*NCOL];      // (N, 384, 5120) 126MB
__device__ float g_spart[16*48*400];             // score partials per t-chunk
__device__ float g_att[48*400];                  // (N*S, VP, VP)
__device__ float g_z[(size_t)NB*SS*CT*VPN];      // (N,S,C*T,VP)  252MB
__device__ float g_y[(size_t)NB*CCH*NCOL];       // (N, C, T*VP)   84MB
__device__ float g_bn[2*CCH];                    // mean, rstd

// ---------------- packed fp32x2 helpers ----------------
typedef unsigned long long u64;
__device__ __forceinline__ u64 dup2(float x){ u64 r; asm("mov.b64 %0, {%1,%1};" : "=l"(r) : "f"(x)); return r; }
__device__ __forceinline__ u64 pk2(float x, float y){ u64 r; asm("mov.b64 %0, {%1,%2};" : "=l"(r) : "f"(x), "f"(y)); return r; }
__device__ __forceinline__ void fma2(u64 &d, u64 a, u64 b){ asm("fma.rn.f32x2 %0, %1, %2, %0;" : "+l"(d) : "l"(a), "l"(b)); }
__device__ __forceinline__ float2 up2(u64 v){ float lo, hi; asm("mov.b64 {%0,%1}, %2;" : "=f"(lo), "=f"(hi) : "l"(v)); return make_float2(lo,hi); }

// ---------------- K1: xp = einsum('nctv,vu->nctu', x, w_e) + b_e --------------
// 2 rows (=(n,c,t) triples) per thread; w_e/b_e in smem (broadcast reads).
__global__ void __launch_bounds__(256) k1_xp(const float* __restrict__ x,
                                             const float* __restrict__ w_e,
                                             const float* __restrict__ b_e) {
    __shared__ float sw[VV*VPN];
    __shared__ float sb[VPN];
    int tid = threadIdx.x;
    for (int i = tid; i < VV*VPN; i += 256) sw[i] = w_e[i];   // FIX: 500 > 256, must stride
    if (tid < VPN) sb[tid] = b_e[tid];
    __syncthreads();
    size_t row0 = ((size_t)blockIdx.x * 256 + tid) * 2;   // 2048 blocks cover 1,048,576 rows
    float xr[2][VV];
    #pragma unroll
    for (int r = 0; r < 2; r++) {
        const float* xr0 = x + (row0 + r) * VV;
        #pragma unroll
        for (int v = 0; v < VV; v++) xr[r][v] = xr0[v];
    }
    float acc[2][VPN];
    #pragma unroll
    for (int u = 0; u < VPN; u++) { float b = sb[u]; acc[0][u] = b; acc[1][u] = b; }
    #pragma unroll
    for (int v = 0; v < VV; v++) {
        float x0 = xr[0][v], x1 = xr[1][v];
        #pragma unroll
        for (int u = 0; u < VPN; u++) {
            float w = sw[v*VPN + u];
            acc[0][u] += x0 * w;
            acc[1][u] += x1 * w;
        }
    }
    #pragma unroll
    for (int r = 0; r < 2; r++) {
        float* o = &g_xp[(row0 + r) * VPN];
        #pragma unroll
        for (int q = 0; q < 5; q++)
            *(float4*)(o + q*4) = make_float4(acc[r][q*4], acc[r][q*4+1], acc[r][q*4+2], acc[r][q*4+3]);
    }
}

// ---------------- tiled batched GEMM (128x128x16, 8x8 micro in f32x2) ---------
// MODE 0: fa/fb  — A rows: [wa(192x256); wb(192x256)], B = xp[n], C = fab[n]
// MODE 1: y      — A[o][k=s*256+c] = wd[s,o,c],        B = z[n],  C = y[n]
template<int MODE>
__global__ void __launch_bounds__(256) gemm_k(const float* __restrict__ W0,
                                              const float* __restrict__ W1,
                                              const float* __restrict__ bias0,
                                              const float* __restrict__ bias1) {
    constexpr int MM = (MODE == 0) ? M1 : M2;
    constexpr int KD = (MODE == 0) ? KK1 : KK2;
    __shared__ float As[16][132];
    __shared__ float Bs[16][128];

    const float* B    = (MODE == 0) ? g_xp : g_z;
    float*       Cout = (MODE == 0) ? g_fab : g_y;

    int tid = threadIdx.x;
    int n   = blockIdx.z;
    const float* Bn = B    + (size_t)n * KD * NCOL;
    float*       Cn = Cout + (size_t)n * MM * NCOL;

    int row0 = blockIdx.y * 128;
    int col0 = blockIdx.x * 128;
    int tm = tid >> 4, tn = tid & 15;
    int ra = tid >> 2;            // 0..63
    int ka = (tid & 3) << 2;      // 0,4,8,12
    int colb = (tid & 31) << 2;   // 0..124
    int kb = tid >> 5;            // 0..7

    u64 acc[8][4];
    #pragma unroll
    for (int i = 0; i < 8; i++)
        #pragma unroll
        for (int j = 0; j < 4; j++) acc[i][j] = 0ull;

    for (int k0 = 0; k0 < KD; k0 += 16) {
        #pragma unroll
        for (int h = 0; h < 2; h++) {
            int r  = row0 + ra + h*64;
            int kg = k0 + ka;
            const float* ap;
            if (MODE == 0) {
                ap = (r < 192) ? (W0 + r*256 + kg) : (W1 + (r-192)*256 + kg);
            } else {
                int s = kg >> 8, c = kg & 255;
                ap = W0 + s*65536 + r*256 + c;
            }
            float4 av = *(const float4*)ap;
            As[ka+0][ra + h*64] = av.x;
            As[ka+1][ra + h*64] = av.y;
            As[ka+2][ra + h*64] = av.z;
            As[ka+3][ra + h*64] = av.w;
        }
        #pragma unroll
        for (int h = 0; h < 2; h++) {
            int kk = kb + h*8;
            *(float4*)&Bs[kk][colb] = *(const float4*)&Bn[(size_t)(k0+kk)*NCOL + col0 + colb];
        }
        __syncthreads();
        #pragma unroll
        for (int kk = 0; kk < 16; kk++) {
            float4 a0 = *(const float4*)&As[kk][tm*8];
            float4 a1 = *(const float4*)&As[kk][tm*8 + 4];
            float4 b0 = *(const float4*)&Bs[kk][tn*8];
            float4 b1 = *(const float4*)&Bs[kk][tn*8 + 4];
            u64 a2[8];
            a2[0]=dup2(a0.x); a2[1]=dup2(a0.y); a2[2]=dup2(a0.z); a2[3]=dup2(a0.w);
            a2[4]=dup2(a1.x); a2[5]=dup2(a1.y); a2[6]=dup2(a1.z); a2[7]=dup2(a1.w);
            u64 b2[4];
            b2[0]=pk2(b0.x,b0.y); b2[1]=pk2(b0.z,b0.w); b2[2]=pk2(b1.x,b1.y); b2[3]=pk2(b1.z,b1.w);
            #pragma unroll
            for (int i = 0; i < 8; i++)
                #pragma unroll
                for (int j = 0; j < 4; j++)
                    fma2(acc[i][j], a2[i], b2[j]);
        }
        __syncthreads();
    }
    #pragma unroll
    for (int i = 0; i < 8; i++) {
        int r = row0 + tm*8 + i;
        float bv;
        if (MODE == 0) bv = (r < 192) ? bias0[r] : bias1[r-192];
        else           bv = bias0[r] + bias0[256 + r] + bias0[512 + r];
        float* cp = &Cn[(size_t)r * NCOL + col0 + tn*8];
        #pragma unroll
        for (int j = 0; j < 4; j++) {
            float2 v = up2(acc[i][j]);
            *(float2*)(cp + 2*j) = make_float2(v.x + bv, v.y + bv);
        }
    }
}

// ---------------- K3: scores partials: scores[v,u] = sum_{i,t} fa[i,t,v]*fb[i,t,u]
// grid (16 t-chunks, 48 (n,s)); deterministic partials, no atomics.
__global__ void __launch_bounds__(512) k3_scores() {
    __shared__ float sfa[8][320];
    __shared__ float sfb[8][320];
    int tid = threadIdx.x;
    int tc = blockIdx.x;           // 0..15 (16 t values each)
    int ns = blockIdx.y;           // n*3+s
    int n = ns / 3, s = ns % 3;
    const float* faB = g_fab + (size_t)n*M1*NCOL + (size_t)(s*64)*NCOL + tc*320;
    const float* fbB = faB + (size_t)192*NCOL;
    float acc = 0.f;
    int v = tid / 20, u = tid % 20;
    for (int ib = 0; ib < 64; ib += 8) {
        for (int idx = tid; idx < 2560; idx += 512) {
            int ii = idx / 320, jj = idx % 320;
            sfa[ii][jj] = faB[(size_t)(ib+ii)*NCOL + jj];
            sfb[ii][jj] = fbB[(size_t)(ib+ii)*NCOL + jj];
        }
        __syncthreads();
        if (tid < 400) {
            #pragma unroll
            for (int ii = 0; ii < 8; ii++)
                #pragma unroll
                for (int t = 0; t < 16; t++)
                    acc += sfa[ii][t*20 + v] * sfb[ii][t*20 + u];
        }
        __syncthreads();
    }
    if (tid < 400)
        g_spart[(tc*48 + ns)*400 + tid] = acc * (1.0f/16384.0f);
}

// ---------------- K4: reduce partials, softmax over v (axis -2), + (A_fix+PA) --
__global__ void __launch_bounds__(512) k4_softmax(const float* __restrict__ PA,
                                                  const float* __restrict__ A_fix) {
    __shared__ float ssc[400];
    int tid = threadIdx.x;
    int ns = blockIdx.x;
    int s = ns % 3;
    if (tid < 400) {
        float a = 0.f;
        #pragma unroll
        for (int tc = 0; tc < 16; tc++) a += g_spart[(tc*48 + ns)*400 + tid];
        ssc[tid] = a;
    }
    __syncthreads();
    if (tid < 20) {
        int u = tid;
        float mx = -1e30f;
        #pragma unroll
        for (int v = 0; v < 20; v++) mx = fmaxf(mx, ssc[v*20 + u]);
        float e[20];
        float sum = 0.f;
        #pragma unroll
        for (int v = 0; v < 20; v++) { e[v] = expf(ssc[v*20 + u] - mx); sum += e[v]; }
        float inv = 1.0f / sum;
        #pragma unroll
        for (int v = 0; v < 20; v++) {
            int ai = (s*20 + v)*20 + u;
            g_att[ns*400 + v*20 + u] = e[v]*inv + A_fix[ai] + PA[ai];
        }
    }
}

// ---------------- K5: z[n,s,k,:] = xp[n,k,:] @ att[n,s]; 2 rows/thread --------
__global__ void __launch_bounds__(256) k5_z() {
    __shared__ float satt[400];
    int tid = threadIdx.x;
    int ns = blockIdx.y;
    int n = ns / 3;
    for (int i = tid; i < 400; i += 256) satt[i] = g_att[ns*400 + i];
    __syncthreads();
    size_t row0 = (size_t)blockIdx.x * 512 + (size_t)tid * 2;   // grid.x = 128 → 65536 rows
    const float* xr0 = &g_xp[((size_t)n*CT + row0)*VPN];
    float xr[2][20];
    #pragma unroll
    for (int r = 0; r < 2; r++)
        #pragma unroll
        for (int q = 0; q < 5; q++)
            *(float4*)&xr[r][q*4] = *(const float4*)(xr0 + r*VPN + q*4);
    float acc[2][20];
    #pragma unroll
    for (int u = 0; u < 20; u++) { acc[0][u] = 0.f; acc[1][u] = 0.f; }
    #pragma unroll
    for (int v = 0; v < 20; v++) {
        float x0 = xr[0][v], x1 = xr[1][v];
        #pragma unroll
        for (int u = 0; u < 20; u++) {
            float a = satt[v*20 + u];
            acc[0][u] += x0 * a;
            acc[1][u] += x1 * a;
        }
    }
    float* zp = &g_z[((size_t)ns*CT + row0)*VPN];
    #pragma unroll
    for (int r = 0; r < 2; r++)
        #pragma unroll
        for (int q = 0; q < 5; q++)
            *(float4*)(zp + r*VPN + q*4) = make_float4(acc[r][q*4], acc[r][q*4+1], acc[r][q*4+2], acc[r][q*4+3]);
}

// ---------------- K7: BN statistics (training mode, biased var) ---------------
__global__ void __launch_bounds__(256) k7_bn() {
    __shared__ double ssum[256];
    __shared__ double ssq[256];
    int o = blockIdx.x, tid = threadIdx.x;
    double s = 0.0, q = 0.0;
    for (int n = 0; n < NB; n++) {
        const float* yp = &g_y[((size_t)n*CCH + o)*NCOL];
        for (int j = tid; j < NCOL; j += 256) { double v = yp[j]; s += v; q += v*v; }
    }
    ssum[tid] = s; ssq[tid] = q;
    __syncthreads();
    for (int st = 128; st > 0; st >>= 1) {
        if (tid < st) { ssum[tid] += ssum[tid+st]; ssq[tid] += ssq[tid+st]; }
        __syncthreads();
    }
    if (tid == 0) {
        double cnt  = (double)NB * NCOL;
        double mean = ssum[0] / cnt;
        double var  = ssq[0] / cnt - mean*mean;
        g_bn[o]       = (float)mean;
        g_bn[256 + o] = (float)(1.0 / sqrt(var + 1e-5));
    }
}

// ---------------- K8: out = relu(BN(y)*gamma+beta + xp) -----------------------
__global__ void __launch_bounds__(256) k8_final(const float* __restrict__ gamma,
                                                const float* __restrict__ beta,
                                                float* __restrict__ out) {
    size_t idx = ((size_t)blockIdx.x * 256 + threadIdx.x) * 4;
    int o = (int)((idx / NCOL) % CCH);     // 4 | 5120 → all 4 lanes share channel
    float rstd = g_bn[256 + o];
    float g = gamma[o] * rstd;
    float b = beta[o] - g_bn[o] * g;
    float4 y  = *(const float4*)&g_y[idx];
    float4 xp = *(const float4*)&g_xp[idx];
    float4 r;
    r.x = fmaxf(y.x*g + b + xp.x, 0.f);
    r.y = fmaxf(y.y*g + b + xp.y, 0.f);
    r.z = fmaxf(y.z*g + b + xp.z, 0.f);
    r.w = fmaxf(y.w*g + b + xp.w, 0.f);
    *(float4*)&out[idx] = r;
}

// ---------------- launch --------------------------------------------------------
extern "C" void kernel_launch(void* const* d_in, const int* in_sizes, int n_in,
                              void* d_out, int out_size) {
    const float* x     = (const float*)d_in[0];
    const float* PA    = (const float*)d_in[1];
    const float* A_fix = (const float*)d_in[2];
    const float* w_e   = (const float*)d_in[3];
    const float* b_e   = (const float*)d_in[4];
    const float* wa    = (const float*)d_in[5];
    const float* ba    = (const float*)d_in[6];
    const float* wb    = (const float*)d_in[7];
    const float* bb    = (const float*)d_in[8];
    const float* wd    = (const float*)d_in[9];
    const float* bd    = (const float*)d_in[10];
    const float* gamma = (const float*)d_in[11];
    const float* beta  = (const float*)d_in[12];
    float* out = (float*)d_out;

    // xp (residual + GEMM1 B operand)
    k1_xp<<<2048, 256>>>(x, w_e, b_e);
    // fa|fb batched GEMM
    gemm_k<0><<<dim3(NCOL/128, M1/128, NB), 256>>>(wa, wb, ba, bb);
    // attention scores + softmax
    k3_scores<<<dim3(16, 48), 512>>>();
    k4_softmax<<<48, 512>>>(PA, A_fix);
    // z = xp @ att
    k5_z<<<dim3(128, 48), 256>>>();
    // y batched GEMM (wd contraction over s,c) + bias
    gemm_k<1><<<dim3(NCOL/128, M2/128, NB), 256>>>(wd, nullptr, bd, nullptr);
    // batchnorm + residual + relu
    k7_bn<<<CCH, 256>>>();
    k8_final<<<20480, 256>>>(gamma, beta, out);
}